// round 5
// baseline (speedup 1.0000x reference)
#include <cuda_runtime.h>
#include <cstdint>
#include <cstddef>

#define T_  512
#define B_  64
#define I_  512
#define H_  512
#define G3  1536   // 3*H

// ---- device scratch (no allocations allowed; device globals are fine) ----
__device__ float g_Gx[2ull * T_ * B_ * G3];    // x@Wih^T + bih, per dir
__device__ float g_hhi[2][2][B_ * H_];         // tf32-hi of h  [dir][parity][b*512+j]
__device__ float g_hlo[2][2][B_ * H_];         // tf32-lo of h
__device__ int   g_cnt[2][T_][8];              // producer flags: [dir][step][chunk]

// ---------------------------------------------------------------------------
// helpers
// ---------------------------------------------------------------------------
__device__ __forceinline__ float tf32_rna(float x) {
    unsigned u;
    asm("cvt.rna.tf32.f32 %0, %1;" : "=r"(u) : "f"(x));
    return __uint_as_float(u);
}

__device__ __forceinline__ void mma8(float* d, const unsigned* a, const unsigned* b) {
    asm volatile(
        "mma.sync.aligned.m16n8k8.row.col.f32.tf32.tf32.f32 "
        "{%0,%1,%2,%3},{%4,%5,%6,%7},{%8,%9},{%0,%1,%2,%3};"
        : "+f"(d[0]), "+f"(d[1]), "+f"(d[2]), "+f"(d[3])
        : "r"(a[0]), "r"(a[1]), "r"(a[2]), "r"(a[3]), "r"(b[0]), "r"(b[1]));
}

__device__ __forceinline__ unsigned fu(float x) { return __float_as_uint(x); }

__device__ __forceinline__ void split4(float4 v, float4& hi, float4& lo) {
    hi.x = tf32_rna(v.x); lo.x = tf32_rna(v.x - hi.x);
    hi.y = tf32_rna(v.y); lo.y = tf32_rna(v.y - hi.y);
    hi.z = tf32_rna(v.z); lo.z = tf32_rna(v.z - hi.z);
    hi.w = tf32_rna(v.w); lo.w = tf32_rna(v.w - hi.w);
}

// ---------------------------------------------------------------------------
// Phase 1: Gx = inp @ Wih^T + bih   (M=32768, N=1536 per dir, K=512)
// tf32x3 mma, block tile 128x64, K-chunk 32. Also zeroes g_cnt for phase 2.
// ---------------------------------------------------------------------------
__global__ __launch_bounds__(256) void gemm_gi(
    const float* __restrict__ inp,
    const float* __restrict__ Wf, const float* __restrict__ Wb,
    const float* __restrict__ bf, const float* __restrict__ bb)
{
    // zero the phase-2 flags (2*512*8 ints) using the x==0,z==0 block column
    if (blockIdx.z == 0 && blockIdx.x == 0) {
        int idx = blockIdx.y * 256 + threadIdx.x;
        if (idx < 2 * T_ * 8) ((int*)g_cnt)[idx] = 0;
    }

    extern __shared__ float sm[];
    float* Ah = sm;                 // [128][36]
    float* Al = Ah + 128 * 36;
    float* Bh = Al + 128 * 36;      // [64][36]
    float* Bl = Bh + 64 * 36;

    const int dir = blockIdx.z;
    const float* __restrict__ W    = dir ? Wb : Wf;
    const float* __restrict__ bias = dir ? bb : bf;
    float* __restrict__ C = g_Gx + (size_t)dir * ((size_t)T_ * B_ * G3);

    const int m0 = blockIdx.y * 128;
    const int n0 = blockIdx.x * 64;

    const int tid  = threadIdx.x;
    const int warp = tid >> 5, lane = tid & 31;
    const int mw = warp >> 1, nw = warp & 1;
    const int g4 = lane >> 2, t4 = lane & 3;

    float acc[2][4][4];
#pragma unroll
    for (int m = 0; m < 2; m++)
#pragma unroll
        for (int n = 0; n < 4; n++)
#pragma unroll
            for (int i = 0; i < 4; i++) acc[m][n][i] = 0.f;

    for (int k0 = 0; k0 < I_; k0 += 32) {
#pragma unroll
        for (int i = 0; i < 4; i++) {
            int idx4 = tid + i * 256;
            int r = idx4 >> 3, q = idx4 & 7;
            float4 v = *(const float4*)(inp + (size_t)(m0 + r) * I_ + k0 + q * 4);
            float4 hi, lo; split4(v, hi, lo);
            *(float4*)(Ah + r * 36 + q * 4) = hi;
            *(float4*)(Al + r * 36 + q * 4) = lo;
        }
#pragma unroll
        for (int i = 0; i < 2; i++) {
            int idx4 = tid + i * 256;
            int r = idx4 >> 3, q = idx4 & 7;
            float4 v = *(const float4*)(W + (size_t)(n0 + r) * I_ + k0 + q * 4);
            float4 hi, lo; split4(v, hi, lo);
            *(float4*)(Bh + r * 36 + q * 4) = hi;
            *(float4*)(Bl + r * 36 + q * 4) = lo;
        }
        __syncthreads();

#pragma unroll
        for (int k8 = 0; k8 < 4; k8++) {
            const int cc = k8 * 8 + t4;
            unsigned ah[2][4], al[2][4], bhf_[4][2], blf_[4][2];
#pragma unroll
            for (int m = 0; m < 2; m++) {
                int row = mw * 32 + m * 16 + g4;
                ah[m][0] = fu(Ah[row * 36 + cc]);
                ah[m][1] = fu(Ah[(row + 8) * 36 + cc]);
                ah[m][2] = fu(Ah[row * 36 + cc + 4]);
                ah[m][3] = fu(Ah[(row + 8) * 36 + cc + 4]);
                al[m][0] = fu(Al[row * 36 + cc]);
                al[m][1] = fu(Al[(row + 8) * 36 + cc]);
                al[m][2] = fu(Al[row * 36 + cc + 4]);
                al[m][3] = fu(Al[(row + 8) * 36 + cc + 4]);
            }
#pragma unroll
            for (int n = 0; n < 4; n++) {
                int rb = nw * 32 + n * 8 + g4;
                bhf_[n][0] = fu(Bh[rb * 36 + cc]);
                bhf_[n][1] = fu(Bh[rb * 36 + cc + 4]);
                blf_[n][0] = fu(Bl[rb * 36 + cc]);
                blf_[n][1] = fu(Bl[rb * 36 + cc + 4]);
            }
#pragma unroll
            for (int m = 0; m < 2; m++)
#pragma unroll
                for (int n = 0; n < 4; n++) {
                    mma8(acc[m][n], ah[m], bhf_[n]);
                    mma8(acc[m][n], ah[m], blf_[n]);
                    mma8(acc[m][n], al[m], bhf_[n]);
                }
        }
        __syncthreads();
    }

#pragma unroll
    for (int m = 0; m < 2; m++)
#pragma unroll
        for (int n = 0; n < 4; n++) {
            int row = m0 + mw * 32 + m * 16 + g4;
            int col = n0 + nw * 32 + n * 8 + 2 * t4;
            float b0 = bias[col], b1 = bias[col + 1];
            *(float2*)(C + (size_t)row * G3 + col) =
                make_float2(acc[m][n][0] + b0, acc[m][n][1] + b1);
            *(float2*)(C + (size_t)(row + 8) * G3 + col) =
                make_float2(acc[m][n][2] + b0, acc[m][n][3] + b1);
        }
}

// ---------------------------------------------------------------------------
// Phase 2: GRU recurrence, tf32x3 mma, flag-based fine-grained sync.
// 128 blocks x 256 thr; block = (dir, 8 j-cols). Per step: 8 K-chunks of 64,
// double-buffered in smem with LDG prefetch into registers; producers publish
// h (pre-split hi/lo) + per-chunk flags; consumers poll flags per chunk.
// No global barrier.
// ---------------------------------------------------------------------------
__global__ __launch_bounds__(256) void gru_rec(
    const float* __restrict__ h0f, const float* __restrict__ h0b,
    const float* __restrict__ Whf, const float* __restrict__ Whb,
    const float* __restrict__ bhf, const float* __restrict__ bhb,
    float* __restrict__ out)
{
    extern __shared__ float sm[];
    float* wh   = sm;                     // [24][516]
    float* wl   = wh + 24 * 516;
    float* hbuf = wl + 24 * 516;          // [2 bufs][hi/lo][64][68]
    float* red  = hbuf + 4 * 64 * 68;     // [4][3][16][8]

    const int dir   = blockIdx.x >> 6;
    const int jblk  = blockIdx.x & 63;
    const int jbase = jblk * 8;
    const int cs    = jblk >> 3;          // own chunk (rotation start)
    const int tid   = threadIdx.x;
    const int warp  = tid >> 5, lane = tid & 31;
    const int mw = warp >> 1, kh = warp & 1;
    const int g4 = lane >> 2, t4 = lane & 3;

    const float* __restrict__ Whh = dir ? Whb : Whf;
    const float* __restrict__ bhh = dir ? bhb : bhf;
    const float* __restrict__ h0  = dir ? h0b : h0f;

    // resident weight slice, hi/lo split
    for (int idx = tid; idx < 3 * 8 * 512; idx += 256) {
        int g = idx >> 12, rem = idx & 4095, jj = rem >> 9, k = rem & 511;
        float v = Whh[(size_t)((g << 9) + jbase + jj) * H_ + k];
        float hi = tf32_rna(v);
        wh[(g * 8 + jj) * 516 + k] = hi;
        wl[(g * 8 + jj) * 516 + k] = tf32_rna(v - hi);
    }

    float bR[2], bZ[2], bN[2];
    {
        int j = jbase + 2 * t4;
        bR[0] = bhh[j];            bR[1] = bhh[j + 1];
        bZ[0] = bhh[H_ + j];       bZ[1] = bhh[H_ + j + 1];
        bN[0] = bhh[2 * H_ + j];   bN[1] = bhh[2 * H_ + j + 1];
    }

    // register-resident previous h for epilogue threads
    float2 hprev[2];
    if (kh == 0) {
        int j = jbase + 2 * t4;
        hprev[0] = *(const float2*)(h0 + (size_t)(mw * 16 + g4) * H_ + j);
        hprev[1] = *(const float2*)(h0 + (size_t)(mw * 16 + g4 + 8) * H_ + j);
    }
    __syncthreads();

    const float* __restrict__ gxBase = g_Gx + (size_t)dir * ((size_t)T_ * B_ * G3);
    const int fb = tid >> 2, fq = tid & 3;    // fill mapping: b-row, 16-float quad

    for (int t = 0; t < T_; t++) {
        const int t_idx = dir ? (T_ - 1 - t) : t;

        // prefetch gate inputs for the epilogue (DRAM latency hidden under MMAs)
        float2 giR[2], giZ[2], giN[2];
        if (kh == 0) {
            const float* __restrict__ gx = gxBase + (size_t)t_idx * B_ * G3;
            const int j = jbase + 2 * t4;
#pragma unroll
            for (int half = 0; half < 2; half++) {
                const int b = mw * 16 + g4 + half * 8;
                giR[half] = *(const float2*)(gx + (size_t)b * G3 + j);
                giZ[half] = *(const float2*)(gx + (size_t)b * G3 + H_ + j);
                giN[half] = *(const float2*)(gx + (size_t)b * G3 + 2 * H_ + j);
            }
        }

        float acc[3][4];
#pragma unroll
        for (int g = 0; g < 3; g++)
#pragma unroll
            for (int i = 0; i < 4; i++) acc[g][i] = 0.f;

        const float* __restrict__ shi = g_hhi[dir][t & 1];
        const float* __restrict__ slo = g_hlo[dir][t & 1];

        // prologue: wait + load regs for first chunk
        float4 rh[4], rl[4];
        {
            const int c = cs;
            if (t == 0) {
#pragma unroll
                for (int i2 = 0; i2 < 4; i2++)
                    rh[i2] = *(const float4*)(h0 + (size_t)fb * H_ + c * 64 + fq * 16 + i2 * 4);
            } else {
                while (*(volatile const int*)&g_cnt[dir][t][c] < 32) { }
                __threadfence();
#pragma unroll
                for (int i2 = 0; i2 < 4; i2++) {
                    rh[i2] = __ldcg((const float4*)(shi + (size_t)fb * H_ + c * 64 + fq * 16 + i2 * 4));
                    rl[i2] = __ldcg((const float4*)(slo + (size_t)fb * H_ + c * 64 + fq * 16 + i2 * 4));
                }
            }
        }

        for (int i = 0; i < 8; i++) {
            const int c = (cs + i) & 7;
            float* bh = hbuf + (size_t)(i & 1) * 2 * 64 * 68;
            float* bl = bh + 64 * 68;

            // stage regs -> smem buffer
            if (t == 0) {
#pragma unroll
                for (int i2 = 0; i2 < 4; i2++) {
                    float4 hi, lo; split4(rh[i2], hi, lo);
                    *(float4*)(bh + fb * 68 + fq * 16 + i2 * 4) = hi;
                    *(float4*)(bl + fb * 68 + fq * 16 + i2 * 4) = lo;
                }
            } else {
#pragma unroll
                for (int i2 = 0; i2 < 4; i2++) {
                    *(float4*)(bh + fb * 68 + fq * 16 + i2 * 4) = rh[i2];
                    *(float4*)(bl + fb * 68 + fq * 16 + i2 * 4) = rl[i2];
                }
            }
            __syncthreads();

            // prefetch next chunk into regs (in flight during compute)
            if (i < 7) {
                const int cn = (cs + i + 1) & 7;
                if (t == 0) {
#pragma unroll
                    for (int i2 = 0; i2 < 4; i2++)
                        rh[i2] = *(const float4*)(h0 + (size_t)fb * H_ + cn * 64 + fq * 16 + i2 * 4);
                } else {
                    while (*(volatile const int*)&g_cnt[dir][t][cn] < 32) { }
                    __threadfence();
#pragma unroll
                    for (int i2 = 0; i2 < 4; i2++) {
                        rh[i2] = __ldcg((const float4*)(shi + (size_t)fb * H_ + cn * 64 + fq * 16 + i2 * 4));
                        rl[i2] = __ldcg((const float4*)(slo + (size_t)fb * H_ + cn * 64 + fq * 16 + i2 * 4));
                    }
                }
            }

            // compute chunk c
#pragma unroll
            for (int k8 = 0; k8 < 4; k8++) {
                const int cc  = kh * 32 + k8 * 8 + t4;
                const int row = mw * 16 + g4;
                unsigned ah[4], al[4];
                ah[0] = fu(bh[row * 68 + cc]);
                ah[1] = fu(bh[(row + 8) * 68 + cc]);
                ah[2] = fu(bh[row * 68 + cc + 4]);
                ah[3] = fu(bh[(row + 8) * 68 + cc + 4]);
                al[0] = fu(bl[row * 68 + cc]);
                al[1] = fu(bl[(row + 8) * 68 + cc]);
                al[2] = fu(bl[row * 68 + cc + 4]);
                al[3] = fu(bl[(row + 8) * 68 + cc + 4]);
                const int wc = c * 64 + cc;
#pragma unroll
                for (int g = 0; g < 3; g++) {
                    const int wr = (g * 8 + g4) * 516 + wc;
                    unsigned bh2[2] = { fu(wh[wr]), fu(wh[wr + 4]) };
                    unsigned bl2[2] = { fu(wl[wr]), fu(wl[wr + 4]) };
                    mma8(acc[g], ah, bh2);
                    mma8(acc[g], ah, bl2);
                    mma8(acc[g], al, bh2);
                }
            }
        }

        // split-K reduce
        if (kh == 1) {
#pragma unroll
            for (int g = 0; g < 3; g++) {
                float* rp = red + (size_t)(mw * 3 + g) * 128;
                *(float2*)(rp + g4 * 8 + 2 * t4)       = make_float2(acc[g][0], acc[g][1]);
                *(float2*)(rp + (g4 + 8) * 8 + 2 * t4) = make_float2(acc[g][2], acc[g][3]);
            }
        }
        __syncthreads();

        if (kh == 0) {
#pragma unroll
            for (int g = 0; g < 3; g++) {
                const float* rp = red + (size_t)(mw * 3 + g) * 128;
                float2 v0 = *(const float2*)(rp + g4 * 8 + 2 * t4);
                float2 v1 = *(const float2*)(rp + (g4 + 8) * 8 + 2 * t4);
                acc[g][0] += v0.x; acc[g][1] += v0.y;
                acc[g][2] += v1.x; acc[g][3] += v1.y;
            }
            float* __restrict__ whi = g_hhi[dir][(t + 1) & 1];
            float* __restrict__ wlo = g_hlo[dir][(t + 1) & 1];
            const int j = jbase + 2 * t4;
#pragma unroll
            for (int half = 0; half < 2; half++) {
                const int b = mw * 16 + g4 + half * 8;
                float hn[2];
#pragma unroll
                for (int u = 0; u < 2; u++) {
                    float aR = acc[0][half * 2 + u];
                    float aZ = acc[1][half * 2 + u];
                    float aN = acc[2][half * 2 + u];
                    float gr = u ? giR[half].y : giR[half].x;
                    float gz = u ? giZ[half].y : giZ[half].x;
                    float gn = u ? giN[half].y : giN[half].x;
                    float hq = u ? hprev[half].y : hprev[half].x;
                    float r = 1.f / (1.f + __expf(-(gr + aR + bR[u])));
                    float z = 1.f / (1.f + __expf(-(gz + aZ + bZ[u])));
                    float n = tanhf(gn + r * (aN + bN[u]));
                    hn[u] = (1.f - z) * n + z * hq;
                }
                float2 hv = make_float2(hn[0], hn[1]);
                hprev[half] = hv;
                *(float2*)(out + ((size_t)t_idx * B_ + b) * (2 * H_) + dir * H_ + j) = hv;
                if (t < T_ - 1) {
                    float2 hi2, lo2;
                    hi2.x = tf32_rna(hn[0]); lo2.x = tf32_rna(hn[0] - hi2.x);
                    hi2.y = tf32_rna(hn[1]); lo2.y = tf32_rna(hn[1] - hi2.y);
                    *(float2*)(whi + (size_t)b * H_ + j) = hi2;
                    *(float2*)(wlo + (size_t)b * H_ + j) = lo2;
                } else {
                    *(float2*)(out + (size_t)T_ * B_ * 2 * H_
                               + (size_t)dir * B_ * H_ + (size_t)b * H_ + j) = hv;
                }
            }
            if (t < T_ - 1) {
                __syncwarp();
                if (lane == 0) {
                    __threadfence();
                    atomicAdd(&g_cnt[dir][t + 1][cs], 1);
                }
            }
        }
    }
}

// ---------------------------------------------------------------------------
extern "C" void kernel_launch(void* const* d_in, const int* in_sizes, int n_in,
                              void* d_out, int out_size)
{
    (void)in_sizes; (void)n_in; (void)out_size;
    const float* inp  = (const float*)d_in[0];
    const float* h0f  = (const float*)d_in[1];
    const float* h0b  = (const float*)d_in[2];
    const float* Wihf = (const float*)d_in[3];
    const float* Whhf = (const float*)d_in[4];
    const float* bihf = (const float*)d_in[5];
    const float* bhhf = (const float*)d_in[6];
    const float* Wihb = (const float*)d_in[7];
    const float* Whhb = (const float*)d_in[8];
    const float* bihb = (const float*)d_in[9];
    const float* bhhb = (const float*)d_in[10];
    float* out = (float*)d_out;

    cudaFuncSetAttribute(gemm_gi, cudaFuncAttributeMaxDynamicSharedMemorySize, 55296);
    cudaFuncSetAttribute(gru_rec, cudaFuncAttributeMaxDynamicSharedMemorySize, 174848);

    dim3 g1(G3 / 64, (T_ * B_) / 128, 2);   // (24, 256, 2)
    gemm_gi<<<g1, 256, 55296>>>(inp, Wihf, Wihb, bihf, bihb);

    gru_rec<<<128, 256, 174848>>>(h0f, h0b, Whhf, Whhb, bhhf, bhhb, out);
}